// round 11
// baseline (speedup 1.0000x reference)
#include <cuda_runtime.h>
#include <math.h>

#define HIDDEN   1024
#define TILE     16
#define HSTRIDE  1026    // words%32==2: conflict-free pass-B; rows 8B-aligned

typedef unsigned long long ull;

__device__ __forceinline__ ull pack2(float lo, float hi) {
    ull r; asm("mov.b64 %0, {%1, %2};" : "=l"(r) : "f"(lo), "f"(hi)); return r;
}
__device__ __forceinline__ void fma2(ull& d, ull a, ull b, ull c) {
    asm("fma.rn.f32x2 %0, %1, %2, %3;" : "=l"(d) : "l"(a), "l"(b), "l"(c));
}
__device__ __forceinline__ void unpack2(ull v, float& lo, float& hi) {
    asm("mov.b64 {%0, %1}, %2;" : "=f"(lo), "=f"(hi) : "l"(v));
}
__device__ __forceinline__ void cp16(unsigned dst, const void* src) {
    asm volatile("cp.async.cg.shared.global [%0], [%1], 16;" :: "r"(dst), "l"(src));
}
__device__ __forceinline__ void cp_commit() {
    asm volatile("cp.async.commit_group;");
}
template<int N> __device__ __forceinline__ void cp_wait() {
    asm volatile("cp.async.wait_group %0;" :: "n"(N));
}

template<int N, int H>
__device__ __forceinline__ void fwht_stage(float* v) {
#pragma unroll
    for (int q = 0; q < N; q += 2 * H)
#pragma unroll
        for (int p = 0; p < H; ++p) {
            float a = v[q + p], b = v[q + H + p];
            v[q + p] = a + b; v[q + H + p] = a - b;
        }
}
__device__ __forceinline__ void fwht16(float* v) {
    fwht_stage<16,1>(v); fwht_stage<16,2>(v); fwht_stage<16,4>(v); fwht_stage<16,8>(v);
}
__device__ __forceinline__ void fwht32(float* v) {
    fwht_stage<32,1>(v); fwht_stage<32,2>(v); fwht_stage<32,4>(v);
    fwht_stage<32,8>(v); fwht_stage<32,16>(v);
}

// ---------------------------------------------------------------------------
// FUSED kernel: LN + BH4 + code/score + table gather, one CTA = 16 rows.
// Row n's gather depends only on row n's codes -> no inter-CTA dependency.
// CTAs de-phase across the grid, overlapping the FMA-bound BH4 section with
// the L2-bound gather section (serial 117us + 80us -> toward max(...)).
// 256 threads, 2 CTAs/SM (~104 KB smem). Warp-private cp.async W staging.
// ---------------------------------------------------------------------------
extern __shared__ float smem[];

__global__ __launch_bounds__(256, 2)
void fused_kernel(const float* __restrict__ x,
                  const float* __restrict__ gamma,
                  const float* __restrict__ beta,
                  const float* __restrict__ W,      // [4][32][32][32]
                  const float* __restrict__ bias,   // [320]
                  const float* __restrict__ tables, // [32*1024, 1024]
                  const float* __restrict__ obias,  // [1024]
                  float* __restrict__ out)
{
    float* sH  = smem;                     // 16 * 1026
    float* sW  = sH + TILE * HSTRIDE;      // 8 warps * 1024 (2 x 512 each)
    float* sMu = sW + 8 * 1024;            // 16
    float* sRs = sMu + 16;                 // 16
    float* sSc = sRs + 16;                 // 32 * 16 scores  [t][r]
    int*   sCd = (int*)(sSc + 32 * 16);    // 32 * 16 codes   [t][r]

    const int tid  = threadIdx.x;
    const int w    = tid >> 5;
    const int lane = tid & 31;
    const int row0 = blockIdx.x * TILE;

    const int row = lane & 15;
    const int jh  = lane >> 4;

    float* sWw = sW + w * 1024;
    const unsigned sWaddr = (unsigned)__cvta_generic_to_shared(sWw);

    // per-warp chunk m (0..31): stage s=m>>3, block c=(m>>1)&3, half h=m&1.
    auto prefetch = [&](int m) {
        const int s = m >> 3, c = (m >> 1) & 3, h = m & 1;
        const float* src = W + ((size_t)(s * 32 + w * 4 + c)) * 1024 + h * 512 + lane * 4;
        const unsigned dst = sWaddr + (unsigned)((h * 512 + lane * 4) * 4);
#pragma unroll
        for (int k = 0; k < 4; ++k)
            cp16(dst + k * 512, src + k * 128);
        cp_commit();
    };

    prefetch(0);   // hidden behind LayerNorm

    // ---------------- LayerNorm: each warp handles 2 rows ----------------
#pragma unroll
    for (int it = 0; it < 2; ++it) {
        const int r = w * 2 + it;
        const float4* xr = (const float4*)(x + (size_t)(row0 + r) * HIDDEN);
        float4 v[8];
        float s = 0.f, ss = 0.f;
#pragma unroll
        for (int c = 0; c < 8; ++c) {
            v[c] = xr[c * 32 + lane];
            s  += v[c].x + v[c].y + v[c].z + v[c].w;
            ss += v[c].x * v[c].x + v[c].y * v[c].y + v[c].z * v[c].z + v[c].w * v[c].w;
        }
#pragma unroll
        for (int o = 16; o; o >>= 1) {
            s  += __shfl_xor_sync(0xffffffffu, s,  o);
            ss += __shfl_xor_sync(0xffffffffu, ss, o);
        }
        const float mu  = s * (1.f / 1024.f);
        const float var = ss * (1.f / 1024.f) - mu * mu;
        const float rs  = rsqrtf(var + 1e-12f);
        if (lane == 0) { sMu[r] = mu; sRs[r] = rs; }
        float* hr = sH + r * HSTRIDE;
#pragma unroll
        for (int c = 0; c < 8; ++c) {
            const int k = c * 128 + lane * 4;
            const float4 gm = ((const float4*)gamma)[c * 32 + lane];
            const float4 bt = ((const float4*)beta )[c * 32 + lane];
            hr[k + 0] = (v[c].x - mu) * rs * gm.x + bt.x;
            hr[k + 1] = (v[c].y - mu) * rs * gm.y + bt.y;
            hr[k + 2] = (v[c].z - mu) * rs * gm.z + bt.z;
            hr[k + 3] = (v[c].w - mu) * rs * gm.w + bt.w;
        }
    }

    // ---------------- 4 BH4 stages (2 CTA barriers each) ----------------
    int m = 0;
    for (int s = 0; s < 4; ++s) {
        __syncthreads();   // sH ready (LN or previous pass B)

#pragma unroll
        for (int c = 0; c < 4; ++c) {
            const int blk = w * 4 + c;
            float* hrow = sH + row * HSTRIDE + blk * 32;

            ull acc2[8];
#pragma unroll
            for (int k = 0; k < 8; ++k) acc2[k] = 0ull;

#pragma unroll
            for (int h = 0; h < 2; ++h) {
                __syncwarp();                 // prior reads of this buffer done
                if (m < 31) { prefetch(m + 1); cp_wait<1>(); }
                else        { cp_wait<0>(); }
                __syncwarp();                 // chunk m visible warp-wide

                const float* wb = sWw + h * 512 + jh * 16;
                const float* hv = hrow + h * 16;
#pragma unroll
                for (int i = 0; i < 16; ++i) {
                    const float hval = hv[i];       // 2-lane LDS broadcast
                    const ull hh = pack2(hval, hval);
                    const ulonglong2* wv = (const ulonglong2*)(wb + i * 32);
                    const ulonglong2 wa = wv[0], wbq = wv[1];
                    fma2(acc2[0], hh, wa.x,  acc2[0]); fma2(acc2[1], hh, wa.y,  acc2[1]);
                    fma2(acc2[2], hh, wbq.x, acc2[2]); fma2(acc2[3], hh, wbq.y, acc2[3]);
                    const ulonglong2 wc = wv[2], wd = wv[3];
                    fma2(acc2[4], hh, wc.x, acc2[4]); fma2(acc2[5], hh, wc.y, acc2[5]);
                    fma2(acc2[6], hh, wd.x, acc2[6]); fma2(acc2[7], hh, wd.y, acc2[7]);
                }
                ++m;
            }

            // fused FWHT pass A: fwht16 on this j-half, then H=16 butterfly
            float va[16];
#pragma unroll
            for (int k = 0; k < 8; ++k) unpack2(acc2[k], va[2 * k], va[2 * k + 1]);
            fwht16(va);
#pragma unroll
            for (int k = 0; k < 16; ++k) {
                const float o = __shfl_xor_sync(0xffffffffu, va[k], 16);
                va[k] = (jh == 0) ? (va[k] + o) : (o - va[k]);
            }
#pragma unroll
            for (int k = 0; k < 16; ++k) hrow[jh * 16 + k] = va[k];
            // no barrier: this warp owns these sH columns exclusively
        }
        __syncthreads();   // all warps' pass-A writes visible

        // FWHT pass B: across 32-blocks (stride 32), conflict-free (HSTRIDE)
#pragma unroll
        for (int g = 0; g < 2; ++g) {
            const int id = tid + g * 256;
            float* p = sH + (id & 15) * HSTRIDE + (id >> 4);
            float vv[32];
#pragma unroll
            for (int c2 = 0; c2 < 32; ++c2) vv[c2] = p[c2 * 32];
            fwht32(vv);
#pragma unroll
            for (int c2 = 0; c2 < 32; ++c2) p[c2 * 32] = vv[c2];
        }
    }
    __syncthreads();

    // ---------------- z -> code, score (into SMEM) ----------------
#pragma unroll
    for (int g = 0; g < 2; ++g) {
        const int id = tid + g * 256;
        const int r  = id & 15;
        const int t  = id >> 4;
        const float mu = sMu[r], rs = sRs[r];
        const float* xrow = x + (size_t)(row0 + r) * HIDDEN;
        int code = 0;
        float sc = 1.f;
#pragma unroll
        for (int j = 0; j < 10; ++j) {
            const int k = t * 10 + j;
            const float xn = (xrow[k] - mu) * rs * gamma[k] + beta[k];
            const float z  = 0.7f * sH[r * HSTRIDE + k] + 0.3f * xn + bias[k];
            if (z > 0.f) code |= (1 << j);
            sc *= 1.f / (1.f + __expf(-fabsf(z)));
        }
        sCd[t * 16 + r] = t * 1024 + code;   // pre-offset into flat table
        sSc[t * 16 + r] = sc;
    }
    __syncthreads();

    // ---------------- gather: out[n] = sum_t score * tables[code] + ob ------
    const float4* tb = (const float4*)tables;
    const float4  ob = ((const float4*)obias)[tid];

#pragma unroll
    for (int rc = 0; rc < 2; ++rc) {     // two chunks of 8 rows: 32 acc regs
        float4 a[8];
#pragma unroll
        for (int r = 0; r < 8; ++r) a[r] = ob;

#pragma unroll 2
        for (int t = 0; t < 32; ++t) {
#pragma unroll
            for (int r = 0; r < 8; ++r) {
                const int   rr = rc * 8 + r;
                const float4 v = __ldg(&tb[(size_t)sCd[t * 16 + rr] * 256 + tid]);
                const float  s = sSc[t * 16 + rr];
                a[r].x += s * v.x; a[r].y += s * v.y;
                a[r].z += s * v.z; a[r].w += s * v.w;
            }
        }
#pragma unroll
        for (int r = 0; r < 8; ++r)
            ((float4*)out)[(size_t)(row0 + rc * 8 + r) * 256 + tid] = a[r];
    }
}

// ---------------------------------------------------------------------------
extern "C" void kernel_launch(void* const* d_in, const int* in_sizes, int n_in,
                              void* d_out, int out_size)
{
    const float* x      = (const float*)d_in[0];   // hidden_states
    const float* gamma  = (const float*)d_in[1];
    const float* beta   = (const float*)d_in[2];
    const float* W      = (const float*)d_in[3];   // bh4_weight
    const float* bias   = (const float*)d_in[4];   // bh4_bias
    const float* tables = (const float*)d_in[5];
    const float* obias  = (const float*)d_in[6];
    float* out = (float*)d_out;

    const int nrows = in_sizes[0] / HIDDEN;        // 8192

    const size_t smem_bytes =
        (size_t)(TILE * HSTRIDE + 8 * 1024 + 32 + 32 * 16 * 2) * sizeof(float); // ~104.3 KB
    cudaFuncSetAttribute(fused_kernel,
                         cudaFuncAttributeMaxDynamicSharedMemorySize,
                         (int)smem_bytes);

    fused_kernel<<<nrows / TILE, 256, smem_bytes>>>(
        x, gamma, beta, W, bias, tables, obias, out);
}

// round 12
// speedup vs baseline: 1.3364x; 1.3364x over previous
#include <cuda_runtime.h>
#include <math.h>

#define HIDDEN   1024
#define NROW_MAX 8192
#define TILE     16
#define HSTRIDE  1026    // words%32==2: conflict-free pass-B; rows 8B-aligned

// scratch (static device arrays; no allocation)
__device__ int   g_code [NROW_MAX * 32];
__device__ float g_score[NROW_MAX * 32];

typedef unsigned long long ull;

__device__ __forceinline__ ull pack2(float lo, float hi) {
    ull r; asm("mov.b64 %0, {%1, %2};" : "=l"(r) : "f"(lo), "f"(hi)); return r;
}
__device__ __forceinline__ void fma2(ull& d, ull a, ull b, ull c) {
    asm("fma.rn.f32x2 %0, %1, %2, %3;" : "=l"(d) : "l"(a), "l"(b), "l"(c));
}
__device__ __forceinline__ void add2(ull& d, ull a, ull b) {
    asm("add.rn.f32x2 %0, %1, %2;" : "=l"(d) : "l"(a), "l"(b));
}
__device__ __forceinline__ void unpack2(ull v, float& lo, float& hi) {
    asm("mov.b64 {%0, %1}, %2;" : "=f"(lo), "=f"(hi) : "l"(v));
}
__device__ __forceinline__ void cp16(unsigned dst, const void* src) {
    asm volatile("cp.async.cg.shared.global [%0], [%1], 16;" :: "r"(dst), "l"(src));
}
__device__ __forceinline__ void cp_commit() {
    asm volatile("cp.async.commit_group;");
}
template<int N> __device__ __forceinline__ void cp_wait() {
    asm volatile("cp.async.wait_group %0;" :: "n"(N));
}

template<int N, int H>
__device__ __forceinline__ void fwht_stage(float* v) {
#pragma unroll
    for (int q = 0; q < N; q += 2 * H)
#pragma unroll
        for (int p = 0; p < H; ++p) {
            float a = v[q + p], b = v[q + H + p];
            v[q + p] = a + b; v[q + H + p] = a - b;
        }
}
__device__ __forceinline__ void fwht16(float* v) {
    fwht_stage<16,1>(v); fwht_stage<16,2>(v); fwht_stage<16,4>(v); fwht_stage<16,8>(v);
}

// packed-f32x2 FWHT32: each ull holds two independent columns.
// a-b computed as fma(b, -1, a) -> exact, bitwise == scalar sub.
__device__ __forceinline__ void fwht32p(ull* v, ull neg1) {
#pragma unroll
    for (int H = 1; H < 32; H <<= 1) {
#pragma unroll
        for (int q = 0; q < 32; q += 2 * H) {
#pragma unroll
            for (int p = 0; p < H; ++p) {
                ull a = v[q + p], b = v[q + H + p], s, d;
                add2(s, a, b);
                fma2(d, b, neg1, a);
                v[q + p] = s; v[q + H + p] = d;
            }
        }
    }
}

// ---------------------------------------------------------------------------
// Phase 1: LN + BH4 (4 stages) + code/score.
// CTA: 16 rows, 256 threads, 2 CTAs/SM (~98.5 KB smem).
// Warp-private cp.async W staging (R8). This round: h preloaded via LDS.64,
// FWHT pass B in packed f32x2 (half the LDS/FADD/STS of scalar).
// ---------------------------------------------------------------------------
extern __shared__ float smem[];

__global__ __launch_bounds__(256, 2)
void phase1_kernel(const float* __restrict__ x,
                   const float* __restrict__ gamma,
                   const float* __restrict__ beta,
                   const float* __restrict__ W,     // [4][32][32][32]
                   const float* __restrict__ bias)  // [320]
{
    float* sH  = smem;                     // 16 * 1026
    float* sW  = sH + TILE * HSTRIDE;      // 8 warps * 1024 (2 x 512 each)
    float* sMu = sW + 8 * 1024;            // 16
    float* sRs = sMu + 16;                 // 16

    const int tid  = threadIdx.x;
    const int w    = tid >> 5;
    const int lane = tid & 31;
    const int row0 = blockIdx.x * TILE;

    const int row = lane & 15;
    const int jh  = lane >> 4;

    float* sWw = sW + w * 1024;
    const unsigned sWaddr = (unsigned)__cvta_generic_to_shared(sWw);

    // per-warp chunk m (0..31): stage s=m>>3, block c=(m>>1)&3, half h=m&1.
    auto prefetch = [&](int m) {
        const int s = m >> 3, c = (m >> 1) & 3, h = m & 1;
        const float* src = W + ((size_t)(s * 32 + w * 4 + c)) * 1024 + h * 512 + lane * 4;
        const unsigned dst = sWaddr + (unsigned)((h * 512 + lane * 4) * 4);
#pragma unroll
        for (int k = 0; k < 4; ++k)
            cp16(dst + k * 512, src + k * 128);
        cp_commit();
    };

    prefetch(0);   // hidden behind LayerNorm

    // ---------------- LayerNorm: each warp handles 2 rows ----------------
#pragma unroll
    for (int it = 0; it < 2; ++it) {
        const int r = w * 2 + it;
        const float4* xr = (const float4*)(x + (size_t)(row0 + r) * HIDDEN);
        float4 v[8];
        float s = 0.f, ss = 0.f;
#pragma unroll
        for (int c = 0; c < 8; ++c) {
            v[c] = xr[c * 32 + lane];
            s  += v[c].x + v[c].y + v[c].z + v[c].w;
            ss += v[c].x * v[c].x + v[c].y * v[c].y + v[c].z * v[c].z + v[c].w * v[c].w;
        }
#pragma unroll
        for (int o = 16; o; o >>= 1) {
            s  += __shfl_xor_sync(0xffffffffu, s,  o);
            ss += __shfl_xor_sync(0xffffffffu, ss, o);
        }
        const float mu  = s * (1.f / 1024.f);
        const float var = ss * (1.f / 1024.f) - mu * mu;
        const float rs  = rsqrtf(var + 1e-12f);
        if (lane == 0) { sMu[r] = mu; sRs[r] = rs; }
        float* hr = sH + r * HSTRIDE;
#pragma unroll
        for (int c = 0; c < 8; ++c) {
            const int k = c * 128 + lane * 4;
            const float4 gm = ((const float4*)gamma)[c * 32 + lane];
            const float4 bt = ((const float4*)beta )[c * 32 + lane];
            hr[k + 0] = (v[c].x - mu) * rs * gm.x + bt.x;
            hr[k + 1] = (v[c].y - mu) * rs * gm.y + bt.y;
            hr[k + 2] = (v[c].z - mu) * rs * gm.z + bt.z;
            hr[k + 3] = (v[c].w - mu) * rs * gm.w + bt.w;
        }
    }

    // ---------------- 4 BH4 stages (2 CTA barriers each) ----------------
    int m = 0;
    for (int s = 0; s < 4; ++s) {
        __syncthreads();   // sH ready (LN or previous pass B)

#pragma unroll
        for (int c = 0; c < 4; ++c) {
            const int blk = w * 4 + c;
            float* hrow = sH + row * HSTRIDE + blk * 32;

            // preload the 32-float h row as 16 LDS.64 (8B-aligned), good MLP
            float2 hvv[16];
            {
                const float2* hp = (const float2*)hrow;
#pragma unroll
                for (int k = 0; k < 16; ++k) hvv[k] = hp[k];
            }

            ull acc2[8];
#pragma unroll
            for (int k = 0; k < 8; ++k) acc2[k] = 0ull;

#pragma unroll
            for (int h = 0; h < 2; ++h) {
                __syncwarp();                 // prior reads of this buffer done
                if (m < 31) { prefetch(m + 1); cp_wait<1>(); }
                else        { cp_wait<0>(); }
                __syncwarp();                 // chunk m visible warp-wide

                const float* wb = sWw + h * 512 + jh * 16;
#pragma unroll
                for (int ii = 0; ii < 8; ++ii) {
                    const float2 hp = hvv[h * 8 + ii];
                    const ull h0 = pack2(hp.x, hp.x);
                    const ull h1 = pack2(hp.y, hp.y);
                    const ulonglong2* wv0 = (const ulonglong2*)(wb + (2 * ii) * 32);
                    const ulonglong2* wv1 = (const ulonglong2*)(wb + (2 * ii + 1) * 32);
                    ulonglong2 a0 = wv0[0], b0 = wv0[1];
                    fma2(acc2[0], h0, a0.x, acc2[0]); fma2(acc2[1], h0, a0.y, acc2[1]);
                    fma2(acc2[2], h0, b0.x, acc2[2]); fma2(acc2[3], h0, b0.y, acc2[3]);
                    a0 = wv0[2]; b0 = wv0[3];
                    fma2(acc2[4], h0, a0.x, acc2[4]); fma2(acc2[5], h0, a0.y, acc2[5]);
                    fma2(acc2[6], h0, b0.x, acc2[6]); fma2(acc2[7], h0, b0.y, acc2[7]);
                    ulonglong2 a1 = wv1[0], b1 = wv1[1];
                    fma2(acc2[0], h1, a1.x, acc2[0]); fma2(acc2[1], h1, a1.y, acc2[1]);
                    fma2(acc2[2], h1, b1.x, acc2[2]); fma2(acc2[3], h1, b1.y, acc2[3]);
                    a1 = wv1[2]; b1 = wv1[3];
                    fma2(acc2[4], h1, a1.x, acc2[4]); fma2(acc2[5], h1, a1.y, acc2[5]);
                    fma2(acc2[6], h1, b1.x, acc2[6]); fma2(acc2[7], h1, b1.y, acc2[7]);
                }
                ++m;
            }

            // fused FWHT pass A: fwht16 on this j-half, then H=16 butterfly
            float va[16];
#pragma unroll
            for (int k = 0; k < 8; ++k) unpack2(acc2[k], va[2 * k], va[2 * k + 1]);
            fwht16(va);
#pragma unroll
            for (int k = 0; k < 16; ++k) {
                const float o = __shfl_xor_sync(0xffffffffu, va[k], 16);
                va[k] = (jh == 0) ? (va[k] + o) : (o - va[k]);
            }
#pragma unroll
            for (int k = 0; k < 16; ++k) hrow[jh * 16 + k] = va[k];
            // no barrier: this warp owns these sH columns exclusively
        }
        __syncthreads();   // all warps' pass-A writes visible

        // FWHT pass B: packed f32x2, thread -> (row, column-pair)
        {
            const int r  = tid & 15;
            const int cp = tid >> 4;
            float* p = sH + r * HSTRIDE + cp * 2;
            const ull neg1 = pack2(-1.f, -1.f);
            ull vv[32];
#pragma unroll
            for (int k = 0; k < 32; ++k) vv[k] = *(const ull*)(p + k * 32);
            fwht32p(vv, neg1);
#pragma unroll
            for (int k = 0; k < 32; ++k) *(ull*)(p + k * 32) = vv[k];
        }
    }
    __syncthreads();

    // ---------------- z -> code, score (xn recomputed from x, mu, rs) -------
#pragma unroll
    for (int g = 0; g < 2; ++g) {
        const int id = tid + g * 256;
        const int r  = id & 15;
        const int t  = id >> 4;
        const int n  = row0 + r;
        const float mu = sMu[r], rs = sRs[r];
        const float* xrow = x + (size_t)n * HIDDEN;
        int code = 0;
        float sc = 1.f;
#pragma unroll
        for (int j = 0; j < 10; ++j) {
            const int k = t * 10 + j;
            const float xn = (xrow[k] - mu) * rs * gamma[k] + beta[k];
            const float z  = 0.7f * sH[r * HSTRIDE + k] + 0.3f * xn + bias[k];
            if (z > 0.f) code |= (1 << j);
            sc *= 1.f / (1.f + __expf(-fabsf(z)));
        }
        g_code [n * 32 + t] = t * 1024 + code;   // pre-offset into flat table
        g_score[n * 32 + t] = sc;
    }
}

// ---------------------------------------------------------------------------
// Phase 2: out[n] = sum_t score[n,t] * tables_flat[code[n,t]] + out_bias
// 4 rows per CTA, table loop OUTERMOST (L2-resident sweep). At the LTS cap
// (~13 TB/s logical gather) — unchanged from R8.
// ---------------------------------------------------------------------------
__global__ __launch_bounds__(256)
void phase2_kernel(const float* __restrict__ tables,
                   const float* __restrict__ obias,
                   float* __restrict__ out)
{
    __shared__ float sc[32][4];
    __shared__ int   cd[32][4];
    const int n0  = blockIdx.x * 4;
    const int tid = threadIdx.x;

    if (tid < 128) {
        const int r = tid & 3;
        const int t = tid >> 2;
        sc[t][r] = g_score[(n0 + r) * 32 + t];
        cd[t][r] = g_code [(n0 + r) * 32 + t];
    }
    __syncthreads();

    const float4 ob = ((const float4*)obias)[tid];
    float4 a[4];
#pragma unroll
    for (int r = 0; r < 4; ++r) a[r] = ob;

    const float4* tb = (const float4*)tables;
#pragma unroll 2
    for (int t = 0; t < 32; ++t) {
#pragma unroll
        for (int r = 0; r < 4; ++r) {
            const float4 v = __ldg(&tb[(size_t)cd[t][r] * 256 + tid]);
            const float  s = sc[t][r];
            a[r].x += s * v.x; a[r].y += s * v.y;
            a[r].z += s * v.z; a[r].w += s * v.w;
        }
    }

#pragma unroll
    for (int r = 0; r < 4; ++r)
        ((float4*)out)[(size_t)(n0 + r) * 256 + tid] = a[r];
}

// ---------------------------------------------------------------------------
extern "C" void kernel_launch(void* const* d_in, const int* in_sizes, int n_in,
                              void* d_out, int out_size)
{
    const float* x      = (const float*)d_in[0];   // hidden_states
    const float* gamma  = (const float*)d_in[1];
    const float* beta   = (const float*)d_in[2];
    const float* W      = (const float*)d_in[3];   // bh4_weight
    const float* bias   = (const float*)d_in[4];   // bh4_bias
    const float* tables = (const float*)d_in[5];
    const float* obias  = (const float*)d_in[6];
    float* out = (float*)d_out;

    const int nrows = in_sizes[0] / HIDDEN;        // 8192

    const size_t smem_bytes =
        (size_t)(TILE * HSTRIDE + 8 * 1024 + 32) * sizeof(float);   // ~98.5 KB
    cudaFuncSetAttribute(phase1_kernel,
                         cudaFuncAttributeMaxDynamicSharedMemorySize,
                         (int)smem_bytes);

    phase1_kernel<<<nrows / TILE, 256, smem_bytes>>>(x, gamma, beta, W, bias);
    phase2_kernel<<<nrows / 4, 256>>>(tables, obias, out);
}

// round 16
// speedup vs baseline: 1.4843x; 1.1107x over previous
#include <cuda_runtime.h>
#include <math.h>

#define HIDDEN   1024
#define NROW_MAX 8192
#define TILE     16
#define HSTRIDE  1026    // words%32==2: conflict-free pass-B; rows 8B-aligned

// scratch (static device arrays; no allocation)
__device__ int   g_code [NROW_MAX * 32];
__device__ float g_score[NROW_MAX * 32];
__device__ volatile int g_flag[NROW_MAX / TILE];   // per-tile ready flags

typedef unsigned long long ull;

__device__ __forceinline__ ull pack2(float lo, float hi) {
    ull r; asm("mov.b64 %0, {%1, %2};" : "=l"(r) : "f"(lo), "f"(hi)); return r;
}
__device__ __forceinline__ void fma2(ull& d, ull a, ull b, ull c) {
    asm("fma.rn.f32x2 %0, %1, %2, %3;" : "=l"(d) : "l"(a), "l"(b), "l"(c));
}
__device__ __forceinline__ void add2(ull& d, ull a, ull b) {
    asm("add.rn.f32x2 %0, %1, %2;" : "=l"(d) : "l"(a), "l"(b));
}
__device__ __forceinline__ void unpack2(ull v, float& lo, float& hi) {
    asm("mov.b64 {%0, %1}, %2;" : "=f"(lo), "=f"(hi) : "l"(v));
}
__device__ __forceinline__ void cp16(unsigned dst, const void* src) {
    asm volatile("cp.async.cg.shared.global [%0], [%1], 16;" :: "r"(dst), "l"(src));
}
__device__ __forceinline__ void cp_commit() {
    asm volatile("cp.async.commit_group;");
}
template<int N> __device__ __forceinline__ void cp_wait() {
    asm volatile("cp.async.wait_group %0;" :: "n"(N));
}

template<int N, int H>
__device__ __forceinline__ void fwht_stage(float* v) {
#pragma unroll
    for (int q = 0; q < N; q += 2 * H)
#pragma unroll
        for (int p = 0; p < H; ++p) {
            float a = v[q + p], b = v[q + H + p];
            v[q + p] = a + b; v[q + H + p] = a - b;
        }
}
__device__ __forceinline__ void fwht16(float* v) {
    fwht_stage<16,1>(v); fwht_stage<16,2>(v); fwht_stage<16,4>(v); fwht_stage<16,8>(v);
}

// packed-f32x2 FWHT32 (a-b as fma(b,-1,a): bitwise == scalar sub)
__device__ __forceinline__ void fwht32p(ull* v, ull neg1) {
#pragma unroll
    for (int H = 1; H < 32; H <<= 1) {
#pragma unroll
        for (int q = 0; q < 32; q += 2 * H) {
#pragma unroll
            for (int p = 0; p < H; ++p) {
                ull a = v[q + p], b = v[q + H + p], s, d;
                add2(s, a, b);
                fma2(d, b, neg1, a);
                v[q + p] = s; v[q + H + p] = d;
            }
        }
    }
}

// ---------------------------------------------------------------------------
__global__ void init_flags_kernel() {
    g_flag[threadIdx.x] = 0;
}

// ---------------------------------------------------------------------------
// Phase 1 (R12 best) + PDL trigger + per-tile release flag.
// ---------------------------------------------------------------------------
extern __shared__ float smem[];

__global__ __launch_bounds__(256, 2)
void phase1_kernel(const float* __restrict__ x,
                   const float* __restrict__ gamma,
                   const float* __restrict__ beta,
                   const float* __restrict__ W,     // [4][32][32][32]
                   const float* __restrict__ bias)  // [320]
{
    // release the dependent (phase2) launch as soon as all p1 CTAs are placed
    asm volatile("griddepcontrol.launch_dependents;");

    float* sH  = smem;                     // 16 * 1026
    float* sW  = sH + TILE * HSTRIDE;      // 8 warps * 1024 (2 x 512 each)
    float* sMu = sW + 8 * 1024;            // 16
    float* sRs = sMu + 16;                 // 16

    const int tid  = threadIdx.x;
    const int w    = tid >> 5;
    const int lane = tid & 31;
    const int row0 = blockIdx.x * TILE;

    const int row = lane & 15;
    const int jh  = lane >> 4;

    float* sWw = sW + w * 1024;
    const unsigned sWaddr = (unsigned)__cvta_generic_to_shared(sWw);

    auto prefetch = [&](int m) {
        const int s = m >> 3, c = (m >> 1) & 3, h = m & 1;
        const float* src = W + ((size_t)(s * 32 + w * 4 + c)) * 1024 + h * 512 + lane * 4;
        const unsigned dst = sWaddr + (unsigned)((h * 512 + lane * 4) * 4);
#pragma unroll
        for (int k = 0; k < 4; ++k)
            cp16(dst + k * 512, src + k * 128);
        cp_commit();
    };

    prefetch(0);   // hidden behind LayerNorm

    // ---------------- LayerNorm: each warp handles 2 rows ----------------
#pragma unroll
    for (int it = 0; it < 2; ++it) {
        const int r = w * 2 + it;
        const float4* xr = (const float4*)(x + (size_t)(row0 + r) * HIDDEN);
        float4 v[8];
        float s = 0.f, ss = 0.f;
#pragma unroll
        for (int c = 0; c < 8; ++c) {
            v[c] = xr[c * 32 + lane];
            s  += v[c].x + v[c].y + v[c].z + v[c].w;
            ss += v[c].x * v[c].x + v[c].y * v[c].y + v[c].z * v[c].z + v[c].w * v[c].w;
        }
#pragma unroll
        for (int o = 16; o; o >>= 1) {
            s  += __shfl_xor_sync(0xffffffffu, s,  o);
            ss += __shfl_xor_sync(0xffffffffu, ss, o);
        }
        const float mu  = s * (1.f / 1024.f);
        const float var = ss * (1.f / 1024.f) - mu * mu;
        const float rs  = rsqrtf(var + 1e-12f);
        if (lane == 0) { sMu[r] = mu; sRs[r] = rs; }
        float* hr = sH + r * HSTRIDE;
#pragma unroll
        for (int c = 0; c < 8; ++c) {
            const int k = c * 128 + lane * 4;
            const float4 gm = ((const float4*)gamma)[c * 32 + lane];
            const float4 bt = ((const float4*)beta )[c * 32 + lane];
            hr[k + 0] = (v[c].x - mu) * rs * gm.x + bt.x;
            hr[k + 1] = (v[c].y - mu) * rs * gm.y + bt.y;
            hr[k + 2] = (v[c].z - mu) * rs * gm.z + bt.z;
            hr[k + 3] = (v[c].w - mu) * rs * gm.w + bt.w;
        }
    }

    // ---------------- 4 BH4 stages (2 CTA barriers each) ----------------
    int m = 0;
    for (int s = 0; s < 4; ++s) {
        __syncthreads();   // sH ready (LN or previous pass B)

#pragma unroll
        for (int c = 0; c < 4; ++c) {
            const int blk = w * 4 + c;
            float* hrow = sH + row * HSTRIDE + blk * 32;

            float2 hvv[16];
            {
                const float2* hp = (const float2*)hrow;
#pragma unroll
                for (int k = 0; k < 16; ++k) hvv[k] = hp[k];
            }

            ull acc2[8];
#pragma unroll
            for (int k = 0; k < 8; ++k) acc2[k] = 0ull;

#pragma unroll
            for (int h = 0; h < 2; ++h) {
                __syncwarp();                 // prior reads of this buffer done
                if (m < 31) { prefetch(m + 1); cp_wait<1>(); }
                else        { cp_wait<0>(); }
                __syncwarp();                 // chunk m visible warp-wide

                const float* wb = sWw + h * 512 + jh * 16;
#pragma unroll
                for (int ii = 0; ii < 8; ++ii) {
                    const float2 hp = hvv[h * 8 + ii];
                    const ull h0 = pack2(hp.x, hp.x);
                    const ull h1 = pack2(hp.y, hp.y);
                    const ulonglong2* wv0 = (const ulonglong2*)(wb + (2 * ii) * 32);
                    const ulonglong2* wv1 = (const ulonglong2*)(wb + (2 * ii + 1) * 32);
                    ulonglong2 a0 = wv0[0], b0 = wv0[1];
                    fma2(acc2[0], h0, a0.x, acc2[0]); fma2(acc2[1], h0, a0.y, acc2[1]);
                    fma2(acc2[2], h0, b0.x, acc2[2]); fma2(acc2[3], h0, b0.y, acc2[3]);
                    a0 = wv0[2]; b0 = wv0[3];
                    fma2(acc2[4], h0, a0.x, acc2[4]); fma2(acc2[5], h0, a0.y, acc2[5]);
                    fma2(acc2[6], h0, b0.x, acc2[6]); fma2(acc2[7], h0, b0.y, acc2[7]);
                    ulonglong2 a1 = wv1[0], b1 = wv1[1];
                    fma2(acc2[0], h1, a1.x, acc2[0]); fma2(acc2[1], h1, a1.y, acc2[1]);
                    fma2(acc2[2], h1, b1.x, acc2[2]); fma2(acc2[3], h1, b1.y, acc2[3]);
                    a1 = wv1[2]; b1 = wv1[3];
                    fma2(acc2[4], h1, a1.x, acc2[4]); fma2(acc2[5], h1, a1.y, acc2[5]);
                    fma2(acc2[6], h1, b1.x, acc2[6]); fma2(acc2[7], h1, b1.y, acc2[7]);
                }
                ++m;
            }

            // fused FWHT pass A
            float va[16];
#pragma unroll
            for (int k = 0; k < 8; ++k) unpack2(acc2[k], va[2 * k], va[2 * k + 1]);
            fwht16(va);
#pragma unroll
            for (int k = 0; k < 16; ++k) {
                const float o = __shfl_xor_sync(0xffffffffu, va[k], 16);
                va[k] = (jh == 0) ? (va[k] + o) : (o - va[k]);
            }
#pragma unroll
            for (int k = 0; k < 16; ++k) hrow[jh * 16 + k] = va[k];
        }
        __syncthreads();   // all warps' pass-A writes visible

        // FWHT pass B: packed f32x2
        {
            const int r  = tid & 15;
            const int cp = tid >> 4;
            float* p = sH + r * HSTRIDE + cp * 2;
            const ull neg1 = pack2(-1.f, -1.f);
            ull vv[32];
#pragma unroll
            for (int k = 0; k < 32; ++k) vv[k] = *(const ull*)(p + k * 32);
            fwht32p(vv, neg1);
#pragma unroll
            for (int k = 0; k < 32; ++k) *(ull*)(p + k * 32) = vv[k];
        }
    }
    __syncthreads();

    // ---------------- z -> code, score ----------------
#pragma unroll
    for (int g = 0; g < 2; ++g) {
        const int id = tid + g * 256;
        const int r  = id & 15;
        const int t  = id >> 4;
        const int n  = row0 + r;
        const float mu = sMu[r], rs = sRs[r];
        const float* xrow = x + (size_t)n * HIDDEN;
        int code = 0;
        float sc = 1.f;
#pragma unroll
        for (int j = 0; j < 10; ++j) {
            const int k = t * 10 + j;
            const float xn = (xrow[k] - mu) * rs * gamma[k] + beta[k];
            const float z  = 0.7f * sH[r * HSTRIDE + k] + 0.3f * xn + bias[k];
            if (z > 0.f) code |= (1 << j);
            sc *= 1.f / (1.f + __expf(-fabsf(z)));
        }
        g_code [n * 32 + t] = t * 1024 + code;
        g_score[n * 32 + t] = sc;
    }

    // release this tile to phase 2
    __threadfence();      // per-thread: codes/scores ordered before flag
    __syncthreads();      // all threads' stores + fences done
    if (tid == 0) g_flag[blockIdx.x] = 1;
}

// ---------------------------------------------------------------------------
// Phase 2 (R12 best) + per-tile spin gate. Launched with PDL (PSS attribute):
// its CTAs are placed during phase1's tail wave and start as soon as their
// tile's codes are committed.
// ---------------------------------------------------------------------------
__global__ __launch_bounds__(256)
void phase2_kernel(const float* __restrict__ tables,
                   const float* __restrict__ obias,
                   float* __restrict__ out)
{
    __shared__ float sc[32][4];
    __shared__ int   cd[32][4];
    const int n0   = blockIdx.x * 4;
    const int tile = blockIdx.x >> 2;   // 4 rows per CTA, 16 rows per tile
    const int tid  = threadIdx.x;

    if (tid == 0) {
        while (g_flag[tile] == 0) __nanosleep(128);
        __threadfence();                // acquire pairing with producer fence
    }
    __syncthreads();

    if (tid < 128) {
        const int r = tid & 3;
        const int t = tid >> 2;
        sc[t][r] = g_score[(n0 + r) * 32 + t];
        cd[t][r] = g_code [(n0 + r) * 32 + t];
    }
    __syncthreads();

    const float4 ob = ((const float4*)obias)[tid];
    float4 a[4];
#pragma unroll
    for (int r = 0; r < 4; ++r) a[r] = ob;

    const float4* tb = (const float4*)tables;
#pragma unroll 2
    for (int t = 0; t < 32; ++t) {
#pragma unroll
        for (int r = 0; r < 4; ++r) {
            const float4 v = __ldg(&tb[(size_t)cd[t][r] * 256 + tid]);
            const float  s = sc[t][r];
            a[r].x += s * v.x; a[r].y += s * v.y;
            a[r].z += s * v.z; a[r].w += s * v.w;
        }
    }

#pragma unroll
    for (int r = 0; r < 4; ++r)
        ((float4*)out)[(size_t)(n0 + r) * 256 + tid] = a[r];
}

// ---------------------------------------------------------------------------
// Single-stream, allocation-free pipeline:
//   init_flags -> phase1 -> phase2[PDL: programmatic stream serialization]
// phase2's launch is released once all phase1 CTAs are placed (trigger at CTA
// start); per-tile flags provide the actual data dependency.
// ---------------------------------------------------------------------------
extern "C" void kernel_launch(void* const* d_in, const int* in_sizes, int n_in,
                              void* d_out, int out_size)
{
    const float* x      = (const float*)d_in[0];
    const float* gamma  = (const float*)d_in[1];
    const float* beta   = (const float*)d_in[2];
    const float* W      = (const float*)d_in[3];
    const float* bias   = (const float*)d_in[4];
    const float* tables = (const float*)d_in[5];
    const float* obias  = (const float*)d_in[6];
    float* out = (float*)d_out;

    const int nrows = in_sizes[0] / HIDDEN;        // 8192
    const int ntiles = nrows / TILE;               // 512

    const size_t smem_bytes =
        (size_t)(TILE * HSTRIDE + 8 * 1024 + 32) * sizeof(float);   // ~98.5 KB
    cudaFuncSetAttribute(phase1_kernel,
                         cudaFuncAttributeMaxDynamicSharedMemorySize,
                         (int)smem_bytes);

    init_flags_kernel<<<1, ntiles>>>();

    phase1_kernel<<<ntiles, 256, smem_bytes>>>(x, gamma, beta, W, bias);

    // phase2 with programmatic stream serialization (PDL)
    cudaLaunchConfig_t cfg = {};
    cfg.gridDim  = dim3(nrows / 4, 1, 1);
    cfg.blockDim = dim3(256, 1, 1);
    cfg.dynamicSmemBytes = 0;
    cfg.stream = 0;
    cudaLaunchAttribute attr[1];
    attr[0].id = cudaLaunchAttributeProgrammaticStreamSerialization;
    attr[0].val.programmaticStreamSerializationAllowed = 1;
    cfg.attrs = attr;
    cfg.numAttrs = 1;
    cudaLaunchKernelEx(&cfg, phase2_kernel, tables, obias, out);
}